// round 5
// baseline (speedup 1.0000x reference)
#include <cuda_runtime.h>
#include <cuda_bf16.h>
#include <cstdint>
#include <cstddef>

// ---------------- problem constants ----------------
#define MTOK   8192            // Bt*S tokens
#define DIN    4096
#define DOUT   4096
#define NEXP   8
#define DK     32
#define RK     16
#define KLORA  (NEXP*RK)       // 128
#define KEXT   (DIN + KLORA)   // 4224
#define NROUT  (NEXP*DK*2 + KLORA)  // 640 = 256 q + 256 k + 128 h
#define SCALING 1.0f

// ---------------- device scratch (static, no allocs allowed) ----------------
__device__ __align__(1024) __nv_bfloat16 g_xh[(size_t)MTOK * KEXT];
__device__ __align__(1024) __nv_bfloat16 g_xl[(size_t)MTOK * KEXT];
__device__ __align__(1024) __nv_bfloat16 g_wh[(size_t)DOUT * KEXT];
__device__ __align__(1024) __nv_bfloat16 g_wl[(size_t)DOUT * KEXT];
__device__ __align__(1024) __nv_bfloat16 g_rh[(size_t)NROUT * DIN];
__device__ __align__(1024) __nv_bfloat16 g_rl[(size_t)NROUT * DIN];
__device__ __align__(1024) float         g_P [(size_t)MTOK * NROUT];

// ---------------- small helpers ----------------
#define DEVFN __device__ __forceinline__

#define SMEM_SWZ(o) ((o) ^ (((o) >> 3) & 0x70))

DEVFN uint32_t smem_u32(const void* p) {
    uint32_t a;
    asm("{ .reg .u64 t; cvta.to.shared.u64 t, %1; cvt.u32.u64 %0, t; }"
        : "=r"(a) : "l"(p));
    return a;
}

DEVFN void split2(float v, __nv_bfloat16& h, __nv_bfloat16& l) {
    h = __float2bfloat16(v);
    l = __float2bfloat16(v - __bfloat162float(h));
}

DEVFN void cp16(uint32_t s, const void* g) {
    asm volatile("cp.async.cg.shared.global [%0], [%1], 16;" :: "r"(s), "l"(g));
}
DEVFN void cp_commit() { asm volatile("cp.async.commit_group;" ::: "memory"); }
DEVFN void cp_wait1()  { asm volatile("cp.async.wait_group 1;"  ::: "memory"); }

DEVFN void ldsm4(uint32_t* r, uint32_t a) {
    asm volatile("ldmatrix.sync.aligned.m8n8.x4.shared.b16 {%0,%1,%2,%3}, [%4];"
                 : "=r"(r[0]), "=r"(r[1]), "=r"(r[2]), "=r"(r[3]) : "r"(a));
}

DEVFN void mma16816(float* c, const uint32_t* a, const uint32_t* b) {
    asm volatile(
        "mma.sync.aligned.m16n8k16.row.col.f32.bf16.bf16.f32 "
        "{%0,%1,%2,%3}, {%4,%5,%6,%7}, {%8,%9}, {%0,%1,%2,%3};"
        : "+f"(c[0]), "+f"(c[1]), "+f"(c[2]), "+f"(c[3])
        : "r"(a[0]), "r"(a[1]), "r"(a[2]), "r"(a[3]), "r"(b[0]), "r"(b[1]));
}

// ---------------- conversion kernels ----------------
__global__ void conv_x_kernel(const float* __restrict__ x) {
    size_t i4 = (size_t)blockIdx.x * blockDim.x + threadIdx.x;
    const size_t tot = (size_t)MTOK * DIN / 4;
    if (i4 >= tot) return;
    float4 v = ((const float4*)x)[i4];
    size_t m = i4 >> 10;              // DIN/4 = 1024 float4 per row
    size_t c = (i4 & 1023) * 4;
    size_t o = m * KEXT + c;
    float f[4] = {v.x, v.y, v.z, v.w};
    __nv_bfloat16 h[4], l[4];
#pragma unroll
    for (int j = 0; j < 4; j++) split2(f[j], h[j], l[j]);
    *(uint2*)&g_xh[o] = *(uint2*)h;
    *(uint2*)&g_xl[o] = *(uint2*)l;
}

__global__ void conv_w_kernel(const float* __restrict__ W, const float* __restrict__ Bm) {
    int o = blockIdx.y;
    int j = blockIdx.x * blockDim.x + threadIdx.x;
    if (j >= KEXT) return;
    float v;
    if (j < DIN) {
        v = W[(size_t)o * DIN + j];
    } else {
        int t = j - DIN;
        int e = t >> 4, r = t & 15;   // RK = 16
        v = Bm[((size_t)e * DOUT + o) * RK + r];
    }
    __nv_bfloat16 h, l; split2(v, h, l);
    size_t idx = (size_t)o * KEXT + j;
    g_wh[idx] = h; g_wl[idx] = l;
}

__global__ void conv_r_kernel(const float* __restrict__ Wq, const float* __restrict__ Wk,
                              const float* __restrict__ A) {
    int row = blockIdx.y;
    int j = blockIdx.x * blockDim.x + threadIdx.x;  // < 4096
    const float* src = (row < 256) ? (Wq + (size_t)row * DIN)
                    : (row < 512) ? (Wk + (size_t)(row - 256) * DIN)
                                  : (A  + (size_t)(row - 512) * DIN);
    float v = src[j];
    __nv_bfloat16 h, l; split2(v, h, l);
    size_t idx = (size_t)row * DIN + j;
    g_rh[idx] = h; g_rl[idx] = l;
}

// ---------------- routing softmax + hw pack ----------------
__global__ void route_kernel() {
    int wid = threadIdx.x >> 5, lane = threadIdx.x & 31;
    int m = blockIdx.x * 8 + wid;
    const float* row = g_P + (size_t)m * NROUT;
    float s[NEXP];
#pragma unroll
    for (int e = 0; e < NEXP; e++) {
        float p = row[e * 32 + lane] * row[256 + e * 32 + lane];
#pragma unroll
        for (int off = 16; off; off >>= 1) p += __shfl_xor_sync(0xffffffffu, p, off);
        s[e] = p * 0.17677669529663687f;   // 1/sqrt(32)
    }
    float mx = s[0];
#pragma unroll
    for (int e = 1; e < NEXP; e++) mx = fmaxf(mx, s[e]);
    float w[NEXP], den = 0.f;
#pragma unroll
    for (int e = 0; e < NEXP; e++) { w[e] = expf(s[e] - mx); den += w[e]; }
    float inv = SCALING / den;
#pragma unroll
    for (int t = lane; t < KLORA; t += 32) {
        int e = t >> 4;
        float hw = w[e] * inv * row[512 + t];
        size_t o = (size_t)m * KEXT + DIN + t;
        g_xh[o] = __float2bfloat16(hw);
        g_xl[o] = __float2bfloat16(0.f);
    }
}

// ---------------- bf16x3 mma.sync GEMM (128x128 tile, K-chunk 64, 3-stage cp.async) ----
// mode 0: routing  P[8192,640]  = x * Wr^T        (K=4096, no bias)
// mode 1: main     out[8192,4096] = [x|hw] * [W|Bm]^T + b  (K=4224)
#define STAGES     3
#define STAGE_BYTES 65536              // 4 tiles x (128 rows x 64 bf16 = 16KB)
#define SMEM_BYTES (STAGES * STAGE_BYTES)

__global__ __launch_bounds__(256, 1) void gemm3(int mode, float* __restrict__ outp,
                                                const float* __restrict__ bias) {
    extern __shared__ char smem[];
    const uint32_t sb = smem_u32(smem);
    const int tid = threadIdx.x, wid = tid >> 5, lid = tid & 31;

    const __nv_bfloat16 *Bh, *Bl;
    int ldb, ldc, kchunks; float* C; bool use_bias;
    if (mode == 0) { Bh = g_rh; Bl = g_rl; ldb = DIN;  C = g_P;  ldc = NROUT; kchunks = DIN / 64;  use_bias = false; }
    else           { Bh = g_wh; Bl = g_wl; ldb = KEXT; C = outp; ldc = DOUT;  kchunks = KEXT / 64; use_bias = true;  }
    const int lda = KEXT;
    const int n0 = blockIdx.x * 128, m0 = blockIdx.y * 128;

    // gmem base pointers for this CTA's panels (byte units)
    const char* pAh = (const char*)(g_xh + (size_t)m0 * lda);
    const char* pAl = (const char*)(g_xl + (size_t)m0 * lda);
    const char* pBh = (const char*)(Bh   + (size_t)n0 * ldb);
    const char* pBl = (const char*)(Bl   + (size_t)n0 * ldb);
    const size_t la = (size_t)lda * 2, lb = (size_t)ldb * 2;

    // per-thread copy pattern: 16 x 16B segments per stage
    // i>>2 selects tile (0=Ah,1=Al,2=Bh,3=Bl); w = tid + (i&3)*256 -> (row, col16)
    auto issue_stage = [&](int ck, int stage) {
        const size_t kb = (size_t)ck * 128;           // 64 bf16 = 128 bytes
        const uint32_t sbase = sb + (uint32_t)stage * STAGE_BYTES;
#pragma unroll
        for (int i = 0; i < 16; i++) {
            const int tile = i >> 2;
            int w = tid + (i & 3) * 256;              // 0..1023
            int r = w >> 3;
            int c = (w & 7) * 16;
            uint32_t so = SMEM_SWZ((uint32_t)(r * 128 + c));
            const char* g = (tile == 0 ? pAh : tile == 1 ? pAl : tile == 2 ? pBh : pBl)
                            + (size_t)r * (tile < 2 ? la : lb) + kb + c;
            cp16(sbase + (uint32_t)tile * 16384u + so, g);
        }
    };

    // warp tiling: 4 warps in m (32 rows each), 2 in n (64 cols each)
    const int warp_m = wid & 3, warp_n = wid >> 2;

    float acc[2][8][4];
#pragma unroll
    for (int a = 0; a < 2; a++)
#pragma unroll
        for (int b = 0; b < 8; b++)
#pragma unroll
            for (int c = 0; c < 4; c++) acc[a][b][c] = 0.f;

    // prologue: prefetch STAGES-1 chunks
    issue_stage(0, 0); cp_commit();
    issue_stage(1, 1); cp_commit();

    // precompute ldmatrix lane offsets (within-tile byte offsets, swizzled per use)
    const int a_row = warp_m * 32 + (lid & 15);           // + mi*16
    const int a_kh  = ((lid >> 4) << 3);                  // + kk
    const int b_row = warp_n * 64 + (lid & 7);            // + nblk*8
    const int b_kh  = (((lid >> 3) & 1) << 3);            // + kk
    const int b_nb  = (lid >> 4);                         // nblk parity

    for (int ck = 0; ck < kchunks; ck++) {
        cp_wait1();
        __syncthreads();
        if (ck + 2 < kchunks) issue_stage(ck + 2, (ck + 2) % STAGES);
        cp_commit();

        const uint32_t sA  = sb + (uint32_t)(ck % STAGES) * STAGE_BYTES;
        const uint32_t sAl = sA + 16384u;
        const uint32_t sBh = sA + 32768u;
        const uint32_t sBl = sA + 49152u;

#pragma unroll
        for (int kk = 0; kk < 64; kk += 16) {
            uint32_t Af[2][4], Lf[2][4], Bf[8][2], Cf[8][2];
            // A hi/lo fragments (2 x m16)
#pragma unroll
            for (int mi = 0; mi < 2; mi++) {
                uint32_t off = SMEM_SWZ((uint32_t)((a_row + mi * 16) * 128 + (kk + a_kh) * 2));
                ldsm4(Af[mi], sA  + off);
                ldsm4(Lf[mi], sAl + off);
            }
            // B hi/lo fragments (8 x n8, loaded 2-at-a-time via x4)
#pragma unroll
            for (int nj = 0; nj < 4; nj++) {
                int nblk = nj * 2 + b_nb;
                uint32_t off = SMEM_SWZ((uint32_t)((b_row + nblk * 8) * 128 + (kk + b_kh) * 2));
                uint32_t t[4];
                ldsm4(t, sBh + off);
                Bf[nj * 2][0] = t[0]; Bf[nj * 2][1] = t[1];
                Bf[nj * 2 + 1][0] = t[2]; Bf[nj * 2 + 1][1] = t[3];
                ldsm4(t, sBl + off);
                Cf[nj * 2][0] = t[0]; Cf[nj * 2][1] = t[1];
                Cf[nj * 2 + 1][0] = t[2]; Cf[nj * 2 + 1][1] = t[3];
            }
            // three split terms: Ah*Bh + Ah*Bl + Al*Bh
#pragma unroll
            for (int mi = 0; mi < 2; mi++)
#pragma unroll
                for (int ni = 0; ni < 8; ni++) mma16816(acc[mi][ni], Af[mi], Bf[ni]);
#pragma unroll
            for (int mi = 0; mi < 2; mi++)
#pragma unroll
                for (int ni = 0; ni < 8; ni++) mma16816(acc[mi][ni], Af[mi], Cf[ni]);
#pragma unroll
            for (int mi = 0; mi < 2; mi++)
#pragma unroll
                for (int ni = 0; ni < 8; ni++) mma16816(acc[mi][ni], Lf[mi], Bf[ni]);
        }
        __syncthreads();
    }

    // epilogue: write 32x64 warp tile
    const int gr = lid >> 2, c0 = (lid & 3) * 2;
#pragma unroll
    for (int mi = 0; mi < 2; mi++) {
        int row = m0 + warp_m * 32 + mi * 16 + gr;
#pragma unroll
        for (int ni = 0; ni < 8; ni++) {
            int col = n0 + warp_n * 64 + ni * 8 + c0;
            float b0 = use_bias ? bias[col]     : 0.f;
            float b1 = use_bias ? bias[col + 1] : 0.f;
            C[(size_t)row * ldc + col]           = acc[mi][ni][0] + b0;
            C[(size_t)row * ldc + col + 1]       = acc[mi][ni][1] + b1;
            C[(size_t)(row + 8) * ldc + col]     = acc[mi][ni][2] + b0;
            C[(size_t)(row + 8) * ldc + col + 1] = acc[mi][ni][3] + b1;
        }
    }
}

// ---------------- launch ----------------
extern "C" void kernel_launch(void* const* d_in, const int* in_sizes, int n_in,
                              void* d_out, int out_size) {
    (void)in_sizes; (void)n_in; (void)out_size;
    const float* x  = (const float*)d_in[0];
    const float* W  = (const float*)d_in[1];
    const float* b  = (const float*)d_in[2];
    const float* Wq = (const float*)d_in[3];
    const float* Wk = (const float*)d_in[4];
    const float* A  = (const float*)d_in[5];
    const float* Bm = (const float*)d_in[6];
    float* out = (float*)d_out;

    cudaFuncSetAttribute(gemm3, cudaFuncAttributeMaxDynamicSharedMemorySize, SMEM_BYTES);

    // 1. fp32 -> bf16 hi/lo splits
    conv_x_kernel<<<(MTOK * (DIN / 4) + 255) / 256, 256>>>(x);
    conv_w_kernel<<<dim3((KEXT + 255) / 256, DOUT), 256>>>(W, Bm);
    conv_r_kernel<<<dim3(DIN / 256, NROUT), 256>>>(Wq, Wk, A);

    // 2. routing GEMM: P = x @ [Wq;Wk;A]^T   (8192 x 640, K=4096)
    gemm3<<<dim3(NROUT / 128, MTOK / 128), 256, SMEM_BYTES>>>(0, nullptr, nullptr);

    // 3. softmax over experts + pack hw into extended-K columns of A
    route_kernel<<<MTOK / 8, 256>>>();

    // 4. main fused GEMM: out = [x|hw] @ [W|Bm]^T + b   (8192 x 4096, K=4224)
    gemm3<<<dim3(DOUT / 128, MTOK / 128), 256, SMEM_BYTES>>>(1, out, b);
}

// round 6
// speedup vs baseline: 2.6301x; 2.6301x over previous
#include <cuda_runtime.h>
#include <cuda_fp16.h>
#include <cstdint>
#include <cstddef>

// ---------------- problem constants ----------------
#define MTOK   8192            // Bt*S tokens
#define DIN    4096
#define DOUT   4096
#define NEXP   8
#define DK     32
#define RK     16
#define KLORA  (NEXP*RK)       // 128
#define KEXT   (DIN + KLORA)   // 4224
#define NROUT  (NEXP*DK*2 + KLORA)  // 640 = 256 q + 256 k + 128 h
#define SCALING 1.0f

// ---------------- device scratch (static, no allocs allowed) ----------------
__device__ __align__(1024) __half g_xh[(size_t)MTOK * KEXT];
__device__ __align__(1024) __half g_wh[(size_t)DOUT * KEXT];
__device__ __align__(1024) __half g_rh[(size_t)NROUT * DIN];
__device__ __align__(1024) float  g_P [(size_t)MTOK * NROUT];

// ---------------- small helpers ----------------
#define DEVFN __device__ __forceinline__

#define SMEM_SWZ(o) ((o) ^ (((o) >> 3) & 0x70))

DEVFN uint32_t smem_u32(const void* p) {
    uint32_t a;
    asm("{ .reg .u64 t; cvta.to.shared.u64 t, %1; cvt.u32.u64 %0, t; }"
        : "=r"(a) : "l"(p));
    return a;
}

DEVFN void cp16(uint32_t s, const void* g) {
    asm volatile("cp.async.cg.shared.global [%0], [%1], 16;" :: "r"(s), "l"(g));
}
DEVFN void cp_commit() { asm volatile("cp.async.commit_group;" ::: "memory"); }
DEVFN void cp_wait1()  { asm volatile("cp.async.wait_group 1;"  ::: "memory"); }

DEVFN void ldsm4(uint32_t* r, uint32_t a) {
    asm volatile("ldmatrix.sync.aligned.m8n8.x4.shared.b16 {%0,%1,%2,%3}, [%4];"
                 : "=r"(r[0]), "=r"(r[1]), "=r"(r[2]), "=r"(r[3]) : "r"(a));
}

DEVFN void mma16816(float* c, const uint32_t* a, const uint32_t* b) {
    asm volatile(
        "mma.sync.aligned.m16n8k16.row.col.f32.f16.f16.f32 "
        "{%0,%1,%2,%3}, {%4,%5,%6,%7}, {%8,%9}, {%0,%1,%2,%3};"
        : "+f"(c[0]), "+f"(c[1]), "+f"(c[2]), "+f"(c[3])
        : "r"(a[0]), "r"(a[1]), "r"(a[2]), "r"(a[3]), "r"(b[0]), "r"(b[1]));
}

// ---------------- conversion kernels (fp32 -> fp16) ----------------
__global__ void conv_x_kernel(const float* __restrict__ x) {
    size_t i4 = (size_t)blockIdx.x * blockDim.x + threadIdx.x;
    const size_t tot = (size_t)MTOK * DIN / 4;
    if (i4 >= tot) return;
    float4 v = ((const float4*)x)[i4];
    size_t m = i4 >> 10;              // DIN/4 = 1024 float4 per row
    size_t c = (i4 & 1023) * 4;
    size_t o = m * KEXT + c;
    __half h[4] = {__float2half(v.x), __float2half(v.y),
                   __float2half(v.z), __float2half(v.w)};
    *(uint2*)&g_xh[o] = *(uint2*)h;
}

__global__ void conv_w_kernel(const float* __restrict__ W, const float* __restrict__ Bm) {
    int o = blockIdx.y;
    int j = blockIdx.x * blockDim.x + threadIdx.x;
    if (j >= KEXT) return;
    float v;
    if (j < DIN) {
        v = W[(size_t)o * DIN + j];
    } else {
        int t = j - DIN;
        int e = t >> 4, r = t & 15;   // RK = 16
        v = Bm[((size_t)e * DOUT + o) * RK + r];
    }
    g_wh[(size_t)o * KEXT + j] = __float2half(v);
}

__global__ void conv_r_kernel(const float* __restrict__ Wq, const float* __restrict__ Wk,
                              const float* __restrict__ A) {
    int row = blockIdx.y;
    int j = blockIdx.x * blockDim.x + threadIdx.x;  // < 4096
    const float* src = (row < 256) ? (Wq + (size_t)row * DIN)
                    : (row < 512) ? (Wk + (size_t)(row - 256) * DIN)
                                  : (A  + (size_t)(row - 512) * DIN);
    g_rh[(size_t)row * DIN + j] = __float2half(src[j]);
}

// ---------------- routing softmax + hw pack ----------------
__global__ void route_kernel() {
    int wid = threadIdx.x >> 5, lane = threadIdx.x & 31;
    int m = blockIdx.x * 8 + wid;
    const float* row = g_P + (size_t)m * NROUT;
    float s[NEXP];
#pragma unroll
    for (int e = 0; e < NEXP; e++) {
        float p = row[e * 32 + lane] * row[256 + e * 32 + lane];
#pragma unroll
        for (int off = 16; off; off >>= 1) p += __shfl_xor_sync(0xffffffffu, p, off);
        s[e] = p * 0.17677669529663687f;   // 1/sqrt(32)
    }
    float mx = s[0];
#pragma unroll
    for (int e = 1; e < NEXP; e++) mx = fmaxf(mx, s[e]);
    float w[NEXP], den = 0.f;
#pragma unroll
    for (int e = 0; e < NEXP; e++) { w[e] = expf(s[e] - mx); den += w[e]; }
    float inv = SCALING / den;
#pragma unroll
    for (int t = lane; t < KLORA; t += 32) {
        int e = t >> 4;
        float hw = w[e] * inv * row[512 + t];
        g_xh[(size_t)m * KEXT + DIN + t] = __float2half(hw);
    }
}

// ---------------- fp16 mma.sync GEMM (128x128 tile, K-chunk 64, 3-stage cp.async) ----
// mode 0: routing  P[8192,640]  = x * Wr^T        (K=4096, no bias)
// mode 1: main     out[8192,4096] = [x|hw] * [W|Bm]^T + b  (K=4224)
#define STAGES      3
#define STAGE_BYTES 32768              // 2 tiles x (128 rows x 64 fp16 = 16KB)
#define SMEM_BYTES  (STAGES * STAGE_BYTES)

__global__ __launch_bounds__(256, 2) void gemm_h(int mode, float* __restrict__ outp,
                                                 const float* __restrict__ bias) {
    extern __shared__ char smem[];
    const uint32_t sb = smem_u32(smem);
    const int tid = threadIdx.x, wid = tid >> 5, lid = tid & 31;

    const __half* Bmat;
    int ldb, ldc, kchunks; float* C; bool use_bias;
    if (mode == 0) { Bmat = g_rh; ldb = DIN;  C = g_P;  ldc = NROUT; kchunks = DIN / 64;  use_bias = false; }
    else           { Bmat = g_wh; ldb = KEXT; C = outp; ldc = DOUT;  kchunks = KEXT / 64; use_bias = true;  }
    const int lda = KEXT;
    const int n0 = blockIdx.x * 128, m0 = blockIdx.y * 128;

    const char* pA = (const char*)(g_xh + (size_t)m0 * lda);
    const char* pB = (const char*)(Bmat + (size_t)n0 * ldb);
    const size_t la = (size_t)lda * 2, lb = (size_t)ldb * 2;

    // per-thread copy pattern: 8 x 16B segments per stage (2 tiles x 4)
    auto issue_stage = [&](int ck, int stage) {
        const size_t kb = (size_t)ck * 128;           // 64 fp16 = 128 bytes
        const uint32_t sbase = sb + (uint32_t)stage * STAGE_BYTES;
#pragma unroll
        for (int i = 0; i < 8; i++) {
            const int tile = i >> 2;                  // 0=A, 1=B
            int w = tid + (i & 3) * 256;              // 0..1023
            int r = w >> 3;
            int c = (w & 7) * 16;
            uint32_t so = SMEM_SWZ((uint32_t)(r * 128 + c));
            const char* g = (tile == 0 ? pA : pB) + (size_t)r * (tile == 0 ? la : lb) + kb + c;
            cp16(sbase + (uint32_t)tile * 16384u + so, g);
        }
    };

    // warp tiling: 4 warps in m (32 rows each), 2 in n (64 cols each)
    const int warp_m = wid & 3, warp_n = wid >> 2;

    float acc[2][8][4];
#pragma unroll
    for (int a = 0; a < 2; a++)
#pragma unroll
        for (int b = 0; b < 8; b++)
#pragma unroll
            for (int c = 0; c < 4; c++) acc[a][b][c] = 0.f;

    issue_stage(0, 0); cp_commit();
    issue_stage(1, 1); cp_commit();

    const int a_row = warp_m * 32 + (lid & 15);           // + mi*16
    const int a_kh  = ((lid >> 4) << 3);                  // + kk
    const int b_row = warp_n * 64 + (lid & 7);            // + nblk*8
    const int b_kh  = (((lid >> 3) & 1) << 3);            // + kk
    const int b_nb  = (lid >> 4);                         // nblk parity

    for (int ck = 0; ck < kchunks; ck++) {
        cp_wait1();
        __syncthreads();
        if (ck + 2 < kchunks) issue_stage(ck + 2, (ck + 2) % STAGES);
        cp_commit();

        const uint32_t sA = sb + (uint32_t)(ck % STAGES) * STAGE_BYTES;
        const uint32_t sB = sA + 16384u;

#pragma unroll
        for (int kk = 0; kk < 64; kk += 16) {
            uint32_t Af[2][4], Bf[8][2];
#pragma unroll
            for (int mi = 0; mi < 2; mi++) {
                uint32_t off = SMEM_SWZ((uint32_t)((a_row + mi * 16) * 128 + (kk + a_kh) * 2));
                ldsm4(Af[mi], sA + off);
            }
#pragma unroll
            for (int nj = 0; nj < 4; nj++) {
                int nblk = nj * 2 + b_nb;
                uint32_t off = SMEM_SWZ((uint32_t)((b_row + nblk * 8) * 128 + (kk + b_kh) * 2));
                uint32_t t[4];
                ldsm4(t, sB + off);
                Bf[nj * 2][0]     = t[0]; Bf[nj * 2][1]     = t[1];
                Bf[nj * 2 + 1][0] = t[2]; Bf[nj * 2 + 1][1] = t[3];
            }
#pragma unroll
            for (int mi = 0; mi < 2; mi++)
#pragma unroll
                for (int ni = 0; ni < 8; ni++) mma16816(acc[mi][ni], Af[mi], Bf[ni]);
        }
        __syncthreads();
    }

    // epilogue: write 32x64 warp tile
    const int gr = lid >> 2, c0 = (lid & 3) * 2;
#pragma unroll
    for (int mi = 0; mi < 2; mi++) {
        int row = m0 + warp_m * 32 + mi * 16 + gr;
#pragma unroll
        for (int ni = 0; ni < 8; ni++) {
            int col = n0 + warp_n * 64 + ni * 8 + c0;
            float b0 = use_bias ? bias[col]     : 0.f;
            float b1 = use_bias ? bias[col + 1] : 0.f;
            C[(size_t)row * ldc + col]           = acc[mi][ni][0] + b0;
            C[(size_t)row * ldc + col + 1]       = acc[mi][ni][1] + b1;
            C[(size_t)(row + 8) * ldc + col]     = acc[mi][ni][2] + b0;
            C[(size_t)(row + 8) * ldc + col + 1] = acc[mi][ni][3] + b1;
        }
    }
}

// ---------------- launch ----------------
extern "C" void kernel_launch(void* const* d_in, const int* in_sizes, int n_in,
                              void* d_out, int out_size) {
    (void)in_sizes; (void)n_in; (void)out_size;
    const float* x  = (const float*)d_in[0];
    const float* W  = (const float*)d_in[1];
    const float* b  = (const float*)d_in[2];
    const float* Wq = (const float*)d_in[3];
    const float* Wk = (const float*)d_in[4];
    const float* A  = (const float*)d_in[5];
    const float* Bm = (const float*)d_in[6];
    float* out = (float*)d_out;

    cudaFuncSetAttribute(gemm_h, cudaFuncAttributeMaxDynamicSharedMemorySize, SMEM_BYTES);

    // 1. fp32 -> fp16 conversion/packing
    conv_x_kernel<<<(MTOK * (DIN / 4) + 255) / 256, 256>>>(x);
    conv_w_kernel<<<dim3((KEXT + 255) / 256, DOUT), 256>>>(W, Bm);
    conv_r_kernel<<<dim3(DIN / 256, NROUT), 256>>>(Wq, Wk, A);

    // 2. routing GEMM: P = x @ [Wq;Wk;A]^T   (8192 x 640, K=4096)
    gemm_h<<<dim3(NROUT / 128, MTOK / 128), 256, SMEM_BYTES>>>(0, nullptr, nullptr);

    // 3. softmax over experts + pack hw into extended-K columns of A
    route_kernel<<<MTOK / 8, 256>>>();

    // 4. main fused GEMM: out = [x|hw] @ [W|Bm]^T + b   (8192 x 4096, K=4224)
    gemm_h<<<dim3(DOUT / 128, MTOK / 128), 256, SMEM_BYTES>>>(1, out, b);
}

// round 7
// speedup vs baseline: 2.9029x; 1.1037x over previous
#include <cuda_runtime.h>
#include <cuda_fp16.h>
#include <cstdint>
#include <cstddef>

// ---------------- problem constants ----------------
#define MTOK   8192            // Bt*S tokens
#define DIN    4096
#define DOUT   4096
#define NEXP   8
#define DK     32
#define RK     16
#define KLORA  (NEXP*RK)       // 128
#define KEXT   (DIN + KLORA)   // 4224
#define NROUT  (NEXP*DK*2 + KLORA)  // 640 = 256 q + 256 k + 128 h
#define SCALING 1.0f

// ---------------- device scratch (static, no allocs allowed) ----------------
__device__ __align__(1024) __half g_xh[(size_t)MTOK * KEXT];
__device__ __align__(1024) __half g_wh[(size_t)DOUT * KEXT];
__device__ __align__(1024) __half g_rh[(size_t)NROUT * DIN];
__device__ __align__(1024) float  g_P [(size_t)MTOK * NROUT];

// ---------------- small helpers ----------------
#define DEVFN __device__ __forceinline__

#define SMEM_SWZ(o) ((o) ^ (((o) >> 3) & 0x70))

DEVFN uint32_t smem_u32(const void* p) {
    uint32_t a;
    asm("{ .reg .u64 t; cvta.to.shared.u64 t, %1; cvt.u32.u64 %0, t; }"
        : "=r"(a) : "l"(p));
    return a;
}

DEVFN void cp16(uint32_t s, const void* g) {
    asm volatile("cp.async.cg.shared.global [%0], [%1], 16;" :: "r"(s), "l"(g));
}
DEVFN void cp_commit() { asm volatile("cp.async.commit_group;" ::: "memory"); }
DEVFN void cp_wait1()  { asm volatile("cp.async.wait_group 1;"  ::: "memory"); }

DEVFN void ldsm4(uint32_t* r, uint32_t a) {
    asm volatile("ldmatrix.sync.aligned.m8n8.x4.shared.b16 {%0,%1,%2,%3}, [%4];"
                 : "=r"(r[0]), "=r"(r[1]), "=r"(r[2]), "=r"(r[3]) : "r"(a));
}

DEVFN void mma16816(float* c, const uint32_t* a, const uint32_t* b) {
    asm volatile(
        "mma.sync.aligned.m16n8k16.row.col.f32.f16.f16.f32 "
        "{%0,%1,%2,%3}, {%4,%5,%6,%7}, {%8,%9}, {%0,%1,%2,%3};"
        : "+f"(c[0]), "+f"(c[1]), "+f"(c[2]), "+f"(c[3])
        : "r"(a[0]), "r"(a[1]), "r"(a[2]), "r"(a[3]), "r"(b[0]), "r"(b[1]));
}

// ---------------- conversion kernels (fp32 -> fp16) ----------------
__global__ void conv_x_kernel(const float* __restrict__ x) {
    size_t i4 = (size_t)blockIdx.x * blockDim.x + threadIdx.x;
    const size_t tot = (size_t)MTOK * DIN / 4;
    if (i4 >= tot) return;
    float4 v = ((const float4*)x)[i4];
    size_t m = i4 >> 10;              // DIN/4 = 1024 float4 per row
    size_t c = (i4 & 1023) * 4;
    size_t o = m * KEXT + c;
    __half h[4] = {__float2half(v.x), __float2half(v.y),
                   __float2half(v.z), __float2half(v.w)};
    *(uint2*)&g_xh[o] = *(uint2*)h;
}

__global__ void conv_w_kernel(const float* __restrict__ W) {
    size_t i4 = (size_t)blockIdx.x * blockDim.x + threadIdx.x;
    const size_t tot = (size_t)DOUT * DIN / 4;
    if (i4 >= tot) return;
    float4 v = ((const float4*)W)[i4];
    size_t o = i4 >> 10;              // DIN/4 = 1024 float4 per row
    size_t c = (i4 & 1023) * 4;
    size_t d = o * KEXT + c;
    __half h[4] = {__float2half(v.x), __float2half(v.y),
                   __float2half(v.z), __float2half(v.w)};
    *(uint2*)&g_wh[d] = *(uint2*)h;
}

__global__ void conv_bm_kernel(const float* __restrict__ Bm) {
    int i = blockIdx.x * blockDim.x + threadIdx.x;   // < DOUT*KLORA
    if (i >= DOUT * KLORA) return;
    int o = i >> 7;                 // output row
    int t = i & 127;                // lora col
    int e = t >> 4, r = t & 15;     // RK = 16
    float v = Bm[((size_t)e * DOUT + o) * RK + r];
    g_wh[(size_t)o * KEXT + DIN + t] = __float2half(v);
}

__global__ void conv_r_kernel(const float* __restrict__ Wq, const float* __restrict__ Wk,
                              const float* __restrict__ A) {
    int row = blockIdx.y;
    int j4 = blockIdx.x * blockDim.x + threadIdx.x;  // < 1024
    const float* src = (row < 256) ? (Wq + (size_t)row * DIN)
                    : (row < 512) ? (Wk + (size_t)(row - 256) * DIN)
                                  : (A  + (size_t)(row - 512) * DIN);
    float4 v = ((const float4*)src)[j4];
    __half h[4] = {__float2half(v.x), __float2half(v.y),
                   __float2half(v.z), __float2half(v.w)};
    *(uint2*)&g_rh[(size_t)row * DIN + j4 * 4] = *(uint2*)h;
}

// ---------------- routing softmax + hw pack ----------------
__global__ void route_kernel() {
    int wid = threadIdx.x >> 5, lane = threadIdx.x & 31;
    int m = blockIdx.x * 8 + wid;
    const float* row = g_P + (size_t)m * NROUT;
    float s[NEXP];
#pragma unroll
    for (int e = 0; e < NEXP; e++) {
        float p = row[e * 32 + lane] * row[256 + e * 32 + lane];
#pragma unroll
        for (int off = 16; off; off >>= 1) p += __shfl_xor_sync(0xffffffffu, p, off);
        s[e] = p * 0.17677669529663687f;   // 1/sqrt(32)
    }
    float mx = s[0];
#pragma unroll
    for (int e = 1; e < NEXP; e++) mx = fmaxf(mx, s[e]);
    float w[NEXP], den = 0.f;
#pragma unroll
    for (int e = 0; e < NEXP; e++) { w[e] = expf(s[e] - mx); den += w[e]; }
    float inv = SCALING / den;
#pragma unroll
    for (int t = lane; t < KLORA; t += 32) {
        int e = t >> 4;
        float hw = w[e] * inv * row[512 + t];
        g_xh[(size_t)m * KEXT + DIN + t] = __float2half(hw);
    }
}

// ---------------- fp16 mma.sync GEMM (128x128 tile, K-chunk 64, 3-stage cp.async) ----
// mode 0: routing  P[8192,640]  = x * Wr^T        (K=4096, no bias)
// mode 1: main     out[8192,4096] = [x|hw] * [W|Bm]^T + b  (K=4224)
#define STAGES      3
#define STAGE_BYTES 32768              // 2 tiles x (128 rows x 64 fp16 = 16KB)
#define SMEM_BYTES  (STAGES * STAGE_BYTES)

__global__ __launch_bounds__(256, 2) void gemm_h(int mode, float* __restrict__ outp,
                                                 const float* __restrict__ bias) {
    extern __shared__ char smem[];
    const uint32_t sb = smem_u32(smem);
    const int tid = threadIdx.x, wid = tid >> 5, lid = tid & 31;

    const __half* Bmat;
    int ldb, ldc, kchunks; float* C; bool use_bias;
    if (mode == 0) { Bmat = g_rh; ldb = DIN;  C = g_P;  ldc = NROUT; kchunks = DIN / 64;  use_bias = false; }
    else           { Bmat = g_wh; ldb = KEXT; C = outp; ldc = DOUT;  kchunks = KEXT / 64; use_bias = true;  }
    const int lda = KEXT;
    const int n0 = blockIdx.x * 128, m0 = blockIdx.y * 128;

    const char* pA = (const char*)(g_xh + (size_t)m0 * lda);
    const char* pB = (const char*)(Bmat + (size_t)n0 * ldb);
    const size_t la = (size_t)lda * 2, lb = (size_t)ldb * 2;

    // per-thread copy pattern: 8 x 16B segments per stage (2 tiles x 4)
    auto issue_stage = [&](int ck, int stage) {
        const size_t kb = (size_t)ck * 128;           // 64 fp16 = 128 bytes
        const uint32_t sbase = sb + (uint32_t)stage * STAGE_BYTES;
#pragma unroll
        for (int i = 0; i < 8; i++) {
            const int tile = i >> 2;                  // 0=A, 1=B
            int w = tid + (i & 3) * 256;              // 0..1023
            int r = w >> 3;
            int c = (w & 7) * 16;
            uint32_t so = SMEM_SWZ((uint32_t)(r * 128 + c));
            const char* g = (tile == 0 ? pA : pB) + (size_t)r * (tile == 0 ? la : lb) + kb + c;
            cp16(sbase + (uint32_t)tile * 16384u + so, g);
        }
    };

    // warp tiling: 4 warps in m (32 rows each), 2 in n (64 cols each)
    const int warp_m = wid & 3, warp_n = wid >> 2;

    float acc[2][8][4];
#pragma unroll
    for (int a = 0; a < 2; a++)
#pragma unroll
        for (int b = 0; b < 8; b++)
#pragma unroll
            for (int c = 0; c < 4; c++) acc[a][b][c] = 0.f;

    issue_stage(0, 0); cp_commit();
    issue_stage(1, 1); cp_commit();

    // ---- hoisted ldmatrix addressing ----
    // SWZ(r*128 + c) = r*128 + (c ^ ((r&7)*16)) for c < 128.
    // r&7 is invariant across mi (step 16) and nblk (step 8) -> one XOR mask each.
    const int a_row = warp_m * 32 + (lid & 15);           // + mi*16
    const int a_kh2 = ((lid >> 4) << 3) * 2;              // byte offset of k-half
    const int b_row = warp_n * 64 + (lid & 7);            // + nblk*8
    const int b_kh2 = ((((lid >> 3) & 1) << 3)) * 2;
    const int b_nb  = (lid >> 4);                         // nblk parity
    const uint32_t xa = (uint32_t)((a_row & 7) * 16);
    const uint32_t xb = (uint32_t)((b_row & 7) * 16);
    uint32_t aR[2], bR[4];
#pragma unroll
    for (int mi = 0; mi < 2; mi++) aR[mi] = (uint32_t)((a_row + mi * 16) * 128);
#pragma unroll
    for (int nj = 0; nj < 4; nj++) bR[nj] = (uint32_t)((b_row + (nj * 2 + b_nb) * 8) * 128);

    int rstage = 0, wstage = 2;   // rotating stage indices (avoid % in loop)
    for (int ck = 0; ck < kchunks; ck++) {
        cp_wait1();
        __syncthreads();
        if (ck + 2 < kchunks) issue_stage(ck + 2, wstage);
        cp_commit();
        if (++wstage == STAGES) wstage = 0;

        const uint32_t sA = sb + (uint32_t)rstage * STAGE_BYTES;
        const uint32_t sB = sA + 16384u;
        if (++rstage == STAGES) rstage = 0;

#pragma unroll
        for (int kk = 0; kk < 64; kk += 16) {
            const uint32_t ca = (uint32_t)(kk * 2 + a_kh2) ^ xa;
            const uint32_t cb = (uint32_t)(kk * 2 + b_kh2) ^ xb;
            uint32_t Af[2][4], Bf[8][2];
#pragma unroll
            for (int mi = 0; mi < 2; mi++) ldsm4(Af[mi], sA + aR[mi] + ca);
#pragma unroll
            for (int nj = 0; nj < 4; nj++) {
                uint32_t t[4];
                ldsm4(t, sB + bR[nj] + cb);
                Bf[nj * 2][0]     = t[0]; Bf[nj * 2][1]     = t[1];
                Bf[nj * 2 + 1][0] = t[2]; Bf[nj * 2 + 1][1] = t[3];
            }
#pragma unroll
            for (int mi = 0; mi < 2; mi++)
#pragma unroll
                for (int ni = 0; ni < 8; ni++) mma16816(acc[mi][ni], Af[mi], Bf[ni]);
        }
        // NOTE: no trailing __syncthreads needed — the barrier at the top of the
        // next iteration (before issue_stage overwrites stage (ck+2)%3 == the
        // stage computed at ck-1) provides the required ordering.
    }

    // epilogue: write 32x64 warp tile (float2 stores)
    const int gr = lid >> 2, c0 = (lid & 3) * 2;
#pragma unroll
    for (int mi = 0; mi < 2; mi++) {
        int row = m0 + warp_m * 32 + mi * 16 + gr;
#pragma unroll
        for (int ni = 0; ni < 8; ni++) {
            int col = n0 + warp_n * 64 + ni * 8 + c0;
            float b0 = use_bias ? bias[col]     : 0.f;
            float b1 = use_bias ? bias[col + 1] : 0.f;
            float2 v0 = make_float2(acc[mi][ni][0] + b0, acc[mi][ni][1] + b1);
            float2 v1 = make_float2(acc[mi][ni][2] + b0, acc[mi][ni][3] + b1);
            *(float2*)&C[(size_t)row * ldc + col]       = v0;
            *(float2*)&C[(size_t)(row + 8) * ldc + col] = v1;
        }
    }
}

// ---------------- launch ----------------
extern "C" void kernel_launch(void* const* d_in, const int* in_sizes, int n_in,
                              void* d_out, int out_size) {
    (void)in_sizes; (void)n_in; (void)out_size;
    const float* x  = (const float*)d_in[0];
    const float* W  = (const float*)d_in[1];
    const float* b  = (const float*)d_in[2];
    const float* Wq = (const float*)d_in[3];
    const float* Wk = (const float*)d_in[4];
    const float* A  = (const float*)d_in[5];
    const float* Bm = (const float*)d_in[6];
    float* out = (float*)d_out;

    cudaFuncSetAttribute(gemm_h, cudaFuncAttributeMaxDynamicSharedMemorySize, SMEM_BYTES);

    // 1. fp32 -> fp16 conversion/packing
    conv_x_kernel<<<(MTOK * (DIN / 4) + 255) / 256, 256>>>(x);
    conv_w_kernel<<<(DOUT * (DIN / 4) + 255) / 256, 256>>>(W);
    conv_bm_kernel<<<(DOUT * KLORA + 255) / 256, 256>>>(Bm);
    conv_r_kernel<<<dim3(DIN / 1024, NROUT), 256>>>(Wq, Wk, A);

    // 2. routing GEMM: P = x @ [Wq;Wk;A]^T   (8192 x 640, K=4096)
    gemm_h<<<dim3(NROUT / 128, MTOK / 128), 256, SMEM_BYTES>>>(0, nullptr, nullptr);

    // 3. softmax over experts + pack hw into extended-K columns of A
    route_kernel<<<MTOK / 8, 256>>>();

    // 4. main fused GEMM: out = [x|hw] @ [W|Bm]^T + b   (8192 x 4096, K=4224)
    gemm_h<<<dim3(DOUT / 128, MTOK / 128), 256, SMEM_BYTES>>>(1, out, b);
}